// round 4
// baseline (speedup 1.0000x reference)
#include <cuda_runtime.h>
#include <cuda_bf16.h>
#include <math.h>
#include <stdint.h>

// ----------------------------------------------------------------------------
// MultiScaleDecoder, tensor-core version (mma.sync bf16, fp32 accum).
//   prepass: inputs fp32 -> bf16 (one [49152,512] A matrix), weights -> bf16
//   L1: relu(A @ Wd^T)  M=49152 N=512 K=512 -> scatter X1[65536,384] bf16
//   L2: relu(X1 @ w1^T) M=65536 N=256 K=384 -> scatter X2[262144,64] bf16
//   L3+L4 fused: per block of 8 patches: GEMM K=64 -> smem stage ->
//                w3/sigmoid -> coalesced fp32 output (X3 never hits HBM)
// ----------------------------------------------------------------------------

#define NP 16384
#define L1_M (3 * NP)                 // 49152
#define X1_ROWS (NP * 4)              // 65536
#define X2_ROWS (NP * 16)             // 262144

__device__ __nv_bfloat16 g_Ain[(size_t)L1_M * 512];    // 50.3 MB
__device__ __nv_bfloat16 g_X1[(size_t)X1_ROWS * 384];  // 50.3 MB
__device__ __nv_bfloat16 g_X2[(size_t)X2_ROWS * 64];   // 33.6 MB
__device__ __nv_bfloat16 g_Wd[512 * 512];              // [n][k]
__device__ __nv_bfloat16 g_W1[256 * 384];              // [n][k]
__device__ __nv_bfloat16 g_W2[128 * 64];               // [n][k]

// ---------------------------------------------------------------- prepasses
__global__ __launch_bounds__(256) void f2bf(const float* __restrict__ src,
                                            __nv_bfloat16* __restrict__ dst,
                                            int n) {
    int i = (blockIdx.x * 256 + threadIdx.x) * 4;
    if (i < n) {
        float4 v = *reinterpret_cast<const float4*>(src + i);
        *reinterpret_cast<__nv_bfloat162*>(dst + i)     = __floats2bfloat162_rn(v.x, v.y);
        *reinterpret_cast<__nv_bfloat162*>(dst + i + 2) = __floats2bfloat162_rn(v.z, v.w);
    }
}

// dense_w [k=512][n=512] -> g_Wd [n][k] bf16
__global__ void transpose_w(const float* __restrict__ src,
                            __nv_bfloat16* __restrict__ dst) {
    __shared__ float t[32][33];
    int k0 = blockIdx.y * 32, n0 = blockIdx.x * 32;
    int tx = threadIdx.x, ty = threadIdx.y;  // block (32, 8)
    for (int r = ty; r < 32; r += 8) t[r][tx] = src[(k0 + r) * 512 + n0 + tx];
    __syncthreads();
    for (int r = ty; r < 32; r += 8)
        dst[(size_t)(n0 + r) * 512 + k0 + tx] = __float2bfloat16(t[tx][r]);
}

// ---------------------------------------------------------------- mma utils
__device__ __forceinline__ uint32_t smem_u32(const void* p) {
    return (uint32_t)__cvta_generic_to_shared(p);
}
__device__ __forceinline__ void ldsm4(uint32_t& r0, uint32_t& r1, uint32_t& r2,
                                      uint32_t& r3, uint32_t addr) {
    asm volatile("ldmatrix.sync.aligned.m8n8.x4.shared.b16 {%0,%1,%2,%3}, [%4];\n"
                 : "=r"(r0), "=r"(r1), "=r"(r2), "=r"(r3) : "r"(addr));
}
__device__ __forceinline__ void mma16816(float* c, const uint32_t* a,
                                         const uint32_t* b) {
    asm volatile(
        "mma.sync.aligned.m16n8k16.row.col.f32.bf16.bf16.f32 "
        "{%0,%1,%2,%3}, {%4,%5,%6,%7}, {%8,%9}, {%0,%1,%2,%3};\n"
        : "+f"(c[0]), "+f"(c[1]), "+f"(c[2]), "+f"(c[3])
        : "r"(a[0]), "r"(a[1]), "r"(a[2]), "r"(a[3]), "r"(b[0]), "r"(b[1]));
}
__device__ __forceinline__ void cp16(void* sdst, const void* gsrc) {
    asm volatile("cp.async.cg.shared.global [%0], [%1], 16;\n" ::
                 "r"(smem_u32(sdst)), "l"(gsrc));
}

#define BM 128
#define BN 128
#define BK 32
#define LDP 40  // padded smem row (elems): 80B stride -> conflict-free ldmatrix

// ---------------------------------------------------------------- GEMM + scatter (L1, L2)
template <int EPI>
__global__ __launch_bounds__(256)
void mma_gemm(const __nv_bfloat16* __restrict__ A,
              const __nv_bfloat16* __restrict__ B,
              const float* __restrict__ bias,
              __nv_bfloat16* __restrict__ Out, int M, int N, int K)
{
    __shared__ __align__(16) __nv_bfloat16 As[2][BM * LDP];
    __shared__ __align__(16) __nv_bfloat16 Bs[2][BN * LDP];

    const int tid = threadIdx.x;
    const int warp = tid >> 5, lane = tid & 31;
    const int row0 = blockIdx.y * BM;
    const int col0 = blockIdx.x * BN;
    const int wm = (warp >> 2) * 64;   // warp tile 64x32
    const int wn = (warp & 3) * 32;

    const int NIT = K / BK;

    auto load_stage = [&](int buf, int ko) {
        #pragma unroll
        for (int c = 0; c < 2; c++) {
            int ch = tid + c * 256;            // 0..511
            int r = ch >> 2, cc = (ch & 3) * 8;
            cp16(&As[buf][r * LDP + cc], &A[(size_t)(row0 + r) * K + ko + cc]);
        }
        #pragma unroll
        for (int c = 0; c < 2; c++) {
            int ch = tid + c * 256;
            int r = ch >> 2, cc = (ch & 3) * 8;
            cp16(&Bs[buf][r * LDP + cc], &B[(size_t)(col0 + r) * K + ko + cc]);
        }
        asm volatile("cp.async.commit_group;\n");
    };

    float acc[4][4][4];
    #pragma unroll
    for (int i = 0; i < 4; i++)
        #pragma unroll
        for (int j = 0; j < 4; j++)
            #pragma unroll
            for (int q = 0; q < 4; q++) acc[i][j][q] = 0.f;

    load_stage(0, 0);

    for (int it = 0; it < NIT; it++) {
        if (it + 1 < NIT) {
            load_stage((it + 1) & 1, (it + 1) * BK);
            asm volatile("cp.async.wait_group 1;\n");
        } else {
            asm volatile("cp.async.wait_group 0;\n");
        }
        __syncthreads();

        const int sb = it & 1;
        #pragma unroll
        for (int ks = 0; ks < 2; ks++) {
            const int k0 = ks * 16;
            uint32_t a[4][4], b[4][2];
            #pragma unroll
            for (int i = 0; i < 4; i++) {
                int r = wm + i * 16 + (lane & 15);
                int kk = k0 + ((lane >> 4) << 3);
                ldsm4(a[i][0], a[i][1], a[i][2], a[i][3],
                      smem_u32(&As[sb][r * LDP + kk]));
            }
            #pragma unroll
            for (int jp = 0; jp < 2; jp++) {
                int rB = wn + jp * 16 + ((lane >> 4) << 3) + (lane & 7);
                int kk = k0 + (((lane >> 3) & 1) << 3);
                ldsm4(b[2 * jp][0], b[2 * jp][1], b[2 * jp + 1][0], b[2 * jp + 1][1],
                      smem_u32(&Bs[sb][rB * LDP + kk]));
            }
            #pragma unroll
            for (int i = 0; i < 4; i++)
                #pragma unroll
                for (int j = 0; j < 4; j++) mma16816(acc[i][j], a[i], b[j]);
        }
        __syncthreads();
    }

    // epilogue: bias + relu + scatter, bf162 pair stores
    auto epi_store = [&](int row, int col, float v0, float v1) {
        float b0, b1;
        if (EPI == 1)      { b0 = bias[col];      b1 = bias[col + 1]; }
        else               { b0 = bias[col & 63]; b1 = bias[(col & 63) + 1]; }
        v0 = fmaxf(v0 + b0, 0.f);
        v1 = fmaxf(v1 + b1, 0.f);
        size_t addr;
        if (EPI == 1) {
            const int pos = col >> 7, kc = col & 127;
            const int s = row >> 14, nl = row & (NP - 1);
            addr = ((size_t)(nl * 4 + pos)) * 384 + s * 128 + kc;
        } else {
            const int a_ = col >> 7, c_ = (col >> 6) & 1, f = col & 63;
            const int nn = row >> 2, ii = (row >> 1) & 1, jj = row & 1;
            addr = ((size_t)(nn * 16 + (2 * ii + a_) * 4 + (2 * jj + c_))) * 64 + f;
        }
        *reinterpret_cast<__nv_bfloat162*>(&Out[addr]) = __floats2bfloat162_rn(v0, v1);
    };

    #pragma unroll
    for (int i = 0; i < 4; i++) {
        const int mA = row0 + wm + i * 16 + (lane >> 2);
        #pragma unroll
        for (int j = 0; j < 4; j++) {
            const int nA = col0 + wn + j * 8 + 2 * (lane & 3);
            epi_store(mA,     nA, acc[i][j][0], acc[i][j][1]);
            epi_store(mA + 8, nA, acc[i][j][2], acc[i][j][3]);
        }
    }
}

// ----------------------------------------------------------------------------
// Fused L3 + L4: one block = 128 X2 rows = 8 patches.
// GEMM [128 x 128 x 64] -> stage[512][40] bf16 in smem (X3 rows for 8 patches)
// -> w3 + sigmoid -> out-stage fp32 in smem -> coalesced float4 flush (24 KB).
// ----------------------------------------------------------------------------
__global__ __launch_bounds__(256)
void l3_l4_fused(const __nv_bfloat16* __restrict__ X2,
                 const __nv_bfloat16* __restrict__ W2,   // [128][64] = [n][k]
                 const float* __restrict__ b2,
                 const float* __restrict__ w3, const float* __restrict__ b3,
                 float* __restrict__ out)
{
    // sbuf: [A/B][stage][128*40]; reused after GEMM as stage / out-stage
    __shared__ __align__(16) __nv_bfloat16 sbuf[2][2][BM * LDP];  // 40960 B
    __shared__ float ws[384];
    __shared__ float bsm[3];

    const int tid = threadIdx.x;
    const int warp = tid >> 5, lane = tid & 31;
    const int row0 = blockIdx.x * BM;        // X2 row base; patches nn0 = row0/16
    const int wm = (warp >> 2) * 64;
    const int wn = (warp & 3) * 32;

    for (int i = tid; i < 384; i += 256) ws[i] = w3[i];
    if (tid < 3) bsm[tid] = b3[tid];

    auto load_stage = [&](int buf, int ko) {
        #pragma unroll
        for (int c = 0; c < 2; c++) {
            int ch = tid + c * 256;
            int r = ch >> 2, cc = (ch & 3) * 8;
            cp16(&sbuf[0][buf][r * LDP + cc], &X2[(size_t)(row0 + r) * 64 + ko + cc]);
        }
        #pragma unroll
        for (int c = 0; c < 2; c++) {
            int ch = tid + c * 256;
            int r = ch >> 2, cc = (ch & 3) * 8;
            cp16(&sbuf[1][buf][r * LDP + cc], &W2[(size_t)r * 64 + ko + cc]);
        }
        asm volatile("cp.async.commit_group;\n");
    };

    float acc[4][4][4];
    #pragma unroll
    for (int i = 0; i < 4; i++)
        #pragma unroll
        for (int j = 0; j < 4; j++)
            #pragma unroll
            for (int q = 0; q < 4; q++) acc[i][j][q] = 0.f;

    load_stage(0, 0);
    #pragma unroll
    for (int it = 0; it < 2; it++) {         // K = 64 -> 2 iterations
        if (it == 0) {
            load_stage(1, BK);
            asm volatile("cp.async.wait_group 1;\n");
        } else {
            asm volatile("cp.async.wait_group 0;\n");
        }
        __syncthreads();
        const int sb = it;
        #pragma unroll
        for (int ks = 0; ks < 2; ks++) {
            const int k0 = ks * 16;
            uint32_t a[4][4], b[4][2];
            #pragma unroll
            for (int i = 0; i < 4; i++) {
                int r = wm + i * 16 + (lane & 15);
                int kk = k0 + ((lane >> 4) << 3);
                ldsm4(a[i][0], a[i][1], a[i][2], a[i][3],
                      smem_u32(&sbuf[0][sb][r * LDP + kk]));
            }
            #pragma unroll
            for (int jp = 0; jp < 2; jp++) {
                int rB = wn + jp * 16 + ((lane >> 4) << 3) + (lane & 7);
                int kk = k0 + (((lane >> 3) & 1) << 3);
                ldsm4(b[2 * jp][0], b[2 * jp][1], b[2 * jp + 1][0], b[2 * jp + 1][1],
                      smem_u32(&sbuf[1][sb][rB * LDP + kk]));
            }
            #pragma unroll
            for (int i = 0; i < 4; i++)
                #pragma unroll
                for (int j = 0; j < 4; j++) mma16816(acc[i][j], a[i], b[j]);
        }
        __syncthreads();   // after this, sbuf is dead as A/B pipeline
    }

    // --- stage X3 tile into smem: stage[lrow (0..511)][f (0..31)], bf16, pad 40
    __nv_bfloat16 (*stage)[LDP] = reinterpret_cast<__nv_bfloat16(*)[LDP]>(&sbuf[0][0][0]);

    auto stage_store = [&](int r_loc, int col, float v0, float v1) {
        const int f = col & 31;
        float b0 = b2[f], b1 = b2[f + 1];
        v0 = fmaxf(v0 + b0, 0.f);
        v1 = fmaxf(v1 + b1, 0.f);
        const int a_ = col >> 6, c_ = (col >> 5) & 1;
        const int nl = r_loc >> 4, p = (r_loc >> 2) & 3, q = r_loc & 3;
        const int lrow = nl * 64 + (2 * p + a_) * 8 + (2 * q + c_);
        *reinterpret_cast<__nv_bfloat162*>(&stage[lrow][f]) =
            __floats2bfloat162_rn(v0, v1);
    };

    #pragma unroll
    for (int i = 0; i < 4; i++) {
        const int mL = wm + i * 16 + (lane >> 2);      // local X2 row
        #pragma unroll
        for (int j = 0; j < 4; j++) {
            const int nA = wn + j * 8 + 2 * (lane & 3);
            stage_store(mL,     nA, acc[i][j][0], acc[i][j][1]);
            stage_store(mL + 8, nA, acc[i][j][2], acc[i][j][3]);
        }
    }
    __syncthreads();

    // --- L4: each thread handles rows tid and tid+256. Read both rows into
    //     registers BEFORE reusing sbuf as the fp32 out-stage.
    uint4 xr[2][4];
    #pragma unroll
    for (int h = 0; h < 2; h++) {
        const int r = tid + h * 256;
        const uint4* sp = reinterpret_cast<const uint4*>(&stage[r][0]);
        #pragma unroll
        for (int i = 0; i < 4; i++) xr[h][i] = sp[i];
    }
    __syncthreads();

    float* ostage = reinterpret_cast<float*>(&sbuf[0][0][0]);  // 6144 floats = 24 KB

    #pragma unroll
    for (int h = 0; h < 2; h++) {
        const int r = tid + h * 256;
        float x[32];
        #pragma unroll
        for (int i = 0; i < 16; i++) {
            __nv_bfloat162 pr = reinterpret_cast<const __nv_bfloat162*>(&xr[h][0])[i];
            float2 f2 = __bfloat1622float2(pr);
            x[2 * i] = f2.x; x[2 * i + 1] = f2.y;
        }
        const int nl = r >> 6, P = (r >> 3) & 7, Q = r & 7;
        const int obase = nl * 768;
        #pragma unroll
        for (int o = 0; o < 12; o++) {
            float acc4 = bsm[o % 3];
            #pragma unroll
            for (int k = 0; k < 32; k++) acc4 = fmaf(x[k], ws[o * 32 + k], acc4);
            const float v = 1.f / (1.f + expf(-acc4));
            const int a2 = o / 6, c2 = (o / 3) & 1, ch = o % 3;
            ostage[obase + (2 * P + a2) * 48 + (2 * Q + c2) * 3 + ch] = v;
        }
    }
    __syncthreads();

    // --- coalesced flush: 8 patches * 768 floats, contiguous in out
    float4* gout = reinterpret_cast<float4*>(out + (size_t)blockIdx.x * 6144);
    const float4* so = reinterpret_cast<const float4*>(ostage);
    #pragma unroll
    for (int i = 0; i < 6; i++) gout[tid + i * 256] = so[tid + i * 256];
}

// ---------------------------------------------------------------- host entry
extern "C" void kernel_launch(void* const* d_in, const int* in_sizes, int n_in,
                              void* d_out, int out_size)
{
    const float* in1     = (const float*)d_in[0];
    const float* in2     = (const float*)d_in[1];
    const float* in3     = (const float*)d_in[2];
    const float* dense_w = (const float*)d_in[3];
    const float* dense_b = (const float*)d_in[4];
    const float* w1      = (const float*)d_in[5];
    const float* b1      = (const float*)d_in[6];
    const float* w2      = (const float*)d_in[7];
    const float* b2      = (const float*)d_in[8];
    const float* w3      = (const float*)d_in[9];
    const float* b3      = (const float*)d_in[10];
    float* out           = (float*)d_out;

    __nv_bfloat16 *ain, *x1, *x2, *wd, *w1b, *w2b;
    cudaGetSymbolAddress((void**)&ain, g_Ain);
    cudaGetSymbolAddress((void**)&x1, g_X1);
    cudaGetSymbolAddress((void**)&x2, g_X2);
    cudaGetSymbolAddress((void**)&wd, g_Wd);
    cudaGetSymbolAddress((void**)&w1b, g_W1);
    cudaGetSymbolAddress((void**)&w2b, g_W2);

    const int NIN = NP * 512;  // 8388608 per input
    f2bf<<<NIN / 1024, 256>>>(in1, ain, NIN);
    f2bf<<<NIN / 1024, 256>>>(in2, ain + (size_t)NIN, NIN);
    f2bf<<<NIN / 1024, 256>>>(in3, ain + (size_t)2 * NIN, NIN);
    transpose_w<<<dim3(16, 16), dim3(32, 8)>>>(dense_w, wd);
    f2bf<<<(256 * 384) / 1024, 256>>>(w1, w1b, 256 * 384);
    f2bf<<<(128 * 64) / 1024, 256>>>(w2, w2b, 128 * 64);

    // L1: [49152,512] @ Wd^T[512,512]
    mma_gemm<1><<<dim3(512 / BN, L1_M / BM), 256>>>(ain, wd, dense_b, x1,
                                                    L1_M, 512, 512);
    // L2: [65536,384] @ w1^T[384,256]
    mma_gemm<2><<<dim3(256 / BN, X1_ROWS / BM), 256>>>(x1, w1b, b1, x2,
                                                       X1_ROWS, 256, 384);
    // L3+L4 fused: 2048 blocks of 8 patches each
    l3_l4_fused<<<X2_ROWS / BM, 256>>>(x2, w2b, b2, w3, b3, out);
}